// round 7
// baseline (speedup 1.0000x reference)
#include <cuda_runtime.h>
#include <cuda_fp16.h>
#include <cstdint>

#define NNODE 10000
#define BNUM  4
#define DDIM  128
#define ECAP  262144
#define ND    (NNODE*DDIM)
#define SLOPE 0.01f
#define RPARTS 40

// ---------------- scratch (device globals; no allocation) ----------------
__device__ __align__(16) __half g_xh[BNUM*ND];   // layer activations (fp16, per-batch)
__device__ __align__(16) __half g_Wh[4*DDIM*DDIM]; // gatW[0..2], W2 as fp16
// h interleaved: [n][32 groups][4 batches][4 halves] = 1024 B per node
__device__ __align__(16) __half g_h[BNUM*ND];
__device__ __align__(16) float g_asrcT[NNODE*4]; // [n][b] transposed logits
__device__ __align__(16) float g_adstT[NNODE*4];
__device__ int   g_offs[NNODE+1];
__device__ int   g_cur[NNODE];
__device__ int   g_srcs[ECAP];
__device__ float g_wnsW[3*DDIM];
__device__ float g_bnsW[3*DDIM];
__device__ float g_sembp[RPARTS*BNUM*DDIM];
__device__ float g_rs[BNUM];

// ---------------- mma helpers ----------------
__device__ __forceinline__ uint32_t su(const void* p) {
    return (uint32_t)__cvta_generic_to_shared(p);
}
__device__ __forceinline__ void ldsm4(uint32_t& r0, uint32_t& r1, uint32_t& r2,
                                      uint32_t& r3, uint32_t addr) {
    asm volatile("ldmatrix.sync.aligned.m8n8.x4.shared.b16 {%0,%1,%2,%3}, [%4];"
                 : "=r"(r0), "=r"(r1), "=r"(r2), "=r"(r3) : "r"(addr));
}
__device__ __forceinline__ void ldsm4t(uint32_t& r0, uint32_t& r1, uint32_t& r2,
                                       uint32_t& r3, uint32_t addr) {
    asm volatile("ldmatrix.sync.aligned.m8n8.x4.trans.shared.b16 {%0,%1,%2,%3}, [%4];"
                 : "=r"(r0), "=r"(r1), "=r"(r2), "=r"(r3) : "r"(addr));
}
__device__ __forceinline__ void mma16816(float* c, uint32_t a0, uint32_t a1,
                                         uint32_t a2, uint32_t a3,
                                         uint32_t b0, uint32_t b1) {
    asm volatile(
        "mma.sync.aligned.m16n8k16.row.col.f32.f16.f16.f32 "
        "{%0,%1,%2,%3}, {%4,%5,%6,%7}, {%8,%9}, {%0,%1,%2,%3};"
        : "+f"(c[0]), "+f"(c[1]), "+f"(c[2]), "+f"(c[3])
        : "r"(a0), "r"(a1), "r"(a2), "r"(a3), "r"(b0), "r"(b1));
}

// ---------------- init: prep + zero + weight fp16 conversion ----------------
__global__ void k_init(const float* __restrict__ W, const float* __restrict__ W2,
                       const float* __restrict__ Wns, const float* __restrict__ bns) {
    int bb = blockIdx.x;
    if (bb < 3) {
        int l = bb, c = threadIdx.x;
        if (c < DDIM) {
            const float* Wl = W + l*DDIM*DDIM;
            float aw = 0.f, ab = 0.f;
            for (int k = 0; k < DDIM; k++) {
                float w = Wl[k*DDIM + c];
                aw += Wns[l*DDIM + k]*w;
                ab += bns[l*DDIM + k]*w;
            }
            g_wnsW[l*DDIM + c] = aw;
            g_bnsW[l*DDIM + c] = ab;
        }
    } else if (bb < 43) {
        int i = (bb - 3)*256 + threadIdx.x;
        if (i < NNODE) g_cur[i] = 0;
    } else {
        int i0 = (bb - 43)*1024 + threadIdx.x*4;
        int m = i0 >> 14, off = i0 & 16383;
        const float* src = (m < 3) ? (W + m*16384 + off) : (W2 + off);
        float4 v = *(const float4*)src;
        union { __half2 h[2]; uint2 u; } cv;
        cv.h[0] = __floats2half2_rn(v.x, v.y);
        cv.h[1] = __floats2half2_rn(v.z, v.w);
        *(uint2*)&g_Wh[i0] = cv.u;
    }
}

// ---------------- CSR build ----------------
__global__ void k_hist(const int* __restrict__ ei, int Etot) {
    int e = blockIdx.x*blockDim.x + threadIdx.x;
    if (e < Etot) atomicAdd(&g_cur[ei[Etot + e]], 1);
}
__global__ void k_scan(int Etot) {
    __shared__ int sh[1024];
    const int ITEMS = 10;
    int t = threadIdx.x;
    int base = t*ITEMS;
    int loc[ITEMS]; int sum = 0;
#pragma unroll
    for (int i = 0; i < ITEMS; i++) {
        int idx = base + i;
        int v = (idx < NNODE) ? g_cur[idx] : 0;
        loc[i] = sum; sum += v;
    }
    sh[t] = sum; __syncthreads();
    for (int off = 1; off < 1024; off <<= 1) {
        int v = (t >= off) ? sh[t-off] : 0;
        __syncthreads();
        sh[t] += v;
        __syncthreads();
    }
    int pre = t ? sh[t-1] : 0;
#pragma unroll
    for (int i = 0; i < ITEMS; i++) {
        int idx = base + i;
        if (idx < NNODE) { int o = pre + loc[i]; g_offs[idx] = o; g_cur[idx] = o; }
    }
    if (t == 1023) g_offs[NNODE] = sh[1023];
}
__global__ void k_scatter(const int* __restrict__ ei, int Etot) {
    int e = blockIdx.x*blockDim.x + threadIdx.x;
    if (e < Etot) {
        int d = ei[Etot + e];
        int pos = atomicAdd(&g_cur[d], 1);
        g_srcs[pos] = ei[e];
    }
}

// ---------------- HMMA GEMM (64x128 tile, fp16 in / fp32 acc) ----------------
#define AS_STR 72
#define BS_STR 136
template<int MODE>
__global__ void __launch_bounds__(256)
k_gemm(int widx, const float* __restrict__ strucf,
       const float* __restrict__ state,
       const float* __restrict__ attS, const float* __restrict__ attD,
       const float* __restrict__ b2, const float* __restrict__ W3,
       float* __restrict__ out) {
    __shared__ __align__(16) unsigned char smraw[35840];
    __half* As = (__half*)smraw;                    // [64][72]
    __half* Bs = (__half*)(smraw + 9216);           // [64][136]
    float*  acc_s = (float*)smraw;                  // [64][132] (reused)
    float*  pb = (float*)(smraw + 33792);           // 512 floats of params

    const int tid = threadIdx.x;
    const int lane = tid & 31, warp = tid >> 5;
    const int warpM = warp & 3, warpN = warp >> 2;
    const int b = blockIdx.y;
    const int rowbase = blockIdx.x * 64;

    const size_t xboff = (size_t)b * (size_t)ND;
    const __half* Wh = g_Wh + (size_t)widx * DDIM * DDIM;

    for (int i = tid; i < 512; i += 256) {
        int a = i >> 7, c = i & 127;
        float v;
        if (MODE == 0)
            v = (a == 0) ? g_wnsW[widx*DDIM + c] :
                (a == 1) ? g_bnsW[widx*DDIM + c] :
                (a == 2) ? attS[c] : attD[c];
        else
            v = (a == 0) ? b2[c] : (a == 1) ? W3[DDIM + c] : 0.f;
        pb[i] = v;
    }

    float acc[8][4];
#pragma unroll
    for (int i = 0; i < 8; i++)
#pragma unroll
        for (int j = 0; j < 4; j++) acc[i][j] = 0.f;

    const uint32_t asb = su(As), bsb = su(Bs);

#pragma unroll
    for (int kc = 0; kc < 2; ++kc) {
#pragma unroll
        for (int c = tid; c < 512; c += 256) {
            int r = c >> 3, q = c & 7;
            int rowg = rowbase + r; rowg = rowg < NNODE ? rowg : NNODE-1;
            if (MODE == 0 && widx == 0) {
                // layer 0: read strucEmb fp32 directly, convert on the fly
                const float* srow = strucf + (size_t)rowg*DDIM + kc*64 + q*8;
                float4 v0 = *(const float4*)srow;
                float4 v1 = *(const float4*)(srow + 4);
                union { __half2 h[4]; uint4 u; } cv;
                cv.h[0] = __floats2half2_rn(v0.x, v0.y);
                cv.h[1] = __floats2half2_rn(v0.z, v0.w);
                cv.h[2] = __floats2half2_rn(v1.x, v1.y);
                cv.h[3] = __floats2half2_rn(v1.z, v1.w);
                *(uint4*)&As[r*AS_STR + q*8] = cv.u;
            } else {
                uint4 v = *(const uint4*)(g_xh + xboff + (size_t)rowg*DDIM + kc*64 + q*8);
                *(uint4*)&As[r*AS_STR + q*8] = v;
            }
        }
#pragma unroll
        for (int c = tid; c < 1024; c += 256) {
            int r = c >> 4, q = c & 15;
            *(uint4*)&Bs[r*BS_STR + q*8] = *(const uint4*)(Wh + (size_t)(kc*64 + r)*DDIM + q*8);
        }
        __syncthreads();
#pragma unroll
        for (int ks = 0; ks < 4; ++ks) {
            uint32_t a0, a1, a2, a3;
            uint32_t aaddr = asb + ((warpM*16 + (lane & 15))*AS_STR
                                    + ks*16 + ((lane >> 4) << 3)) * 2;
            ldsm4(a0, a1, a2, a3, aaddr);
#pragma unroll
            for (int nt = 0; nt < 4; ++nt) {
                uint32_t b0, b1, b2r, b3;
                uint32_t baddr = bsb + ((ks*16 + (lane & 15))*BS_STR
                                        + warpN*64 + nt*16 + ((lane >> 4) << 3)) * 2;
                ldsm4t(b0, b1, b2r, b3, baddr);
                mma16816(acc[nt*2],   a0, a1, a2, a3, b0, b1);
                mma16816(acc[nt*2+1], a0, a1, a2, a3, b2r, b3);
            }
        }
        __syncthreads();
    }

    {
        int gr = warpM*16 + (lane >> 2);
        int cb0 = warpN*64 + (lane & 3)*2;
#pragma unroll
        for (int nt8 = 0; nt8 < 8; ++nt8) {
            int cb = cb0 + nt8*8;
            acc_s[gr*132 + cb]       = acc[nt8][0];
            acc_s[gr*132 + cb + 1]   = acc[nt8][1];
            acc_s[(gr+8)*132 + cb]   = acc[nt8][2];
            acc_s[(gr+8)*132 + cb+1] = acc[nt8][3];
        }
    }
    __syncthreads();

    const int r = tid >> 2, seg = tid & 3;
    const int row_g = rowbase + r;
    const int rc = row_g < NNODE ? row_g : NNODE-1;

    if (MODE == 0) {
        float st = state[(size_t)b*NNODE + rc];
        float asr = 0.f, ads = 0.f;
        uint32_t hw[16];
#pragma unroll
        for (int i2 = 0; i2 < 16; i2++) {
            int c = seg*32 + i2*2;
            float v0 = acc_s[r*132 + c]     + st*pb[c]     + pb[128 + c];
            float v1 = acc_s[r*132 + c + 1] + st*pb[c + 1] + pb[129 + c];
            asr += v0*pb[256 + c] + v1*pb[257 + c];
            ads += v0*pb[384 + c] + v1*pb[385 + c];
            __half2 h = __floats2half2_rn(v0, v1);
            hw[i2] = *(uint32_t*)&h;
        }
        asr += __shfl_xor_sync(0xffffffffu, asr, 1);
        asr += __shfl_xor_sync(0xffffffffu, asr, 2);
        ads += __shfl_xor_sync(0xffffffffu, ads, 1);
        ads += __shfl_xor_sync(0xffffffffu, ads, 2);
        if (row_g < NNODE) {
            if (seg == 0) {
                g_asrcT[row_g*4 + b] = asr;
                g_adstT[row_g*4 + b] = ads;
            }
            // interleaved h store: [n][group][batch][4 halves]
            uint32_t* hb = (uint32_t*)g_h;
            size_t base = (size_t)row_g*256 + b*2;
#pragma unroll
            for (int p = 0; p < 8; p++) {
                int g = seg*8 + p;
                uint2 val = {hw[p*2], hw[p*2 + 1]};
                *(uint2*)&hb[base + g*8] = val;
            }
        }
    } else {
        float ra = 0.f;
#pragma unroll
        for (int i = 0; i < 32; i++) {
            int c = seg*32 + i;
            float v = fmaxf(acc_s[r*132 + c] + pb[c], 0.f);
            ra += v * pb[128 + c];
        }
        ra += __shfl_xor_sync(0xffffffffu, ra, 1);
        ra += __shfl_xor_sync(0xffffffffu, ra, 2);
        if (seg == 0 && row_g < NNODE)
            out[(size_t)b*NNODE + row_g] = g_rs[b] + ra;
    }
}

// ---------------- edge softmax + aggregate ----------------
// One warp per dst node, 4 batches fused, interleaved h:
// each lane reads ONE contiguous 32B chunk (2x LDG.128) per edge.
__device__ __forceinline__ void edge_acc2(float a, float ad, uint32_t w0, uint32_t w1,
                                          float4& acc, float& s) {
    float ae = a + ad;
    ae = ae > 0.f ? ae : SLOPE*ae;
    float p = __expf(ae);
    s += p;
    float2 f0 = __half22float2(*(__half2*)&w0);
    float2 f1 = __half22float2(*(__half2*)&w1);
    acc.x += p*f0.x; acc.y += p*f0.y;
    acc.z += p*f1.x; acc.w += p*f1.y;
}

__global__ void __launch_bounds__(256) k_edge(const float* __restrict__ bias) {
    int n = (blockIdx.x*blockDim.x + threadIdx.x) >> 5;
    int lane = threadIdx.x & 31;
    if (n >= NNODE) return;
    int e0 = g_offs[n], e1 = g_offs[n+1];
    const float4 ad = *(const float4*)&g_adstT[n*4];
    const uint4* h4 = (const uint4*)g_h;

    float4 acc0 = {0,0,0,0}, acc1 = {0,0,0,0}, acc2 = {0,0,0,0}, acc3 = {0,0,0,0};
    float s0 = 0.f, s1 = 0.f, s2 = 0.f, s3 = 0.f;

    // depth-2 pipeline
    int sv = __ldg(&g_srcs[e0]);
    float4 as = *(const float4*)&g_asrcT[sv*4];
    uint4 A0 = h4[(size_t)sv*64 + lane*2];
    uint4 A1 = h4[(size_t)sv*64 + lane*2 + 1];

    for (int e = e0; e < e1; ++e) {
        float4 asc = as;
        uint4 c0 = A0, c1 = A1;
        if (e + 1 < e1) {
            sv = __ldg(&g_srcs[e+1]);
            as = *(const float4*)&g_asrcT[sv*4];
            A0 = h4[(size_t)sv*64 + lane*2];
            A1 = h4[(size_t)sv*64 + lane*2 + 1];
        }
        edge_acc2(asc.x, ad.x, c0.x, c0.y, acc0, s0);
        edge_acc2(asc.y, ad.y, c0.z, c0.w, acc1, s1);
        edge_acc2(asc.z, ad.z, c1.x, c1.y, acc2, s2);
        edge_acc2(asc.w, ad.w, c1.z, c1.w, acc3, s3);
    }

    float4 bi = ((const float4*)bias)[lane];
    float4* accs[4] = {&acc0, &acc1, &acc2, &acc3};
    float ss[4] = {s0, s1, s2, s3};
#pragma unroll
    for (int b = 0; b < 4; b++) {
        float inv = 1.f / ss[b];
        float4 a = *accs[b];
        union { uint2 u; __half2 h[2]; } ov;
        ov.h[0] = __floats2half2_rn(fmaxf(a.x*inv + bi.x, 0.f),
                                    fmaxf(a.y*inv + bi.y, 0.f));
        ov.h[1] = __floats2half2_rn(fmaxf(a.z*inv + bi.z, 0.f),
                                    fmaxf(a.w*inv + bi.w, 0.f));
        *(uint2*)(g_xh + (size_t)b*ND + (size_t)n*DDIM + lane*4) = ov.u;
    }
}

// ---------------- final head ----------------
__global__ void k_reduce() {
    int b = blockIdx.y;
    int r0 = blockIdx.x * 250;
    int r1 = r0 + 250; if (r1 > NNODE) r1 = NNODE;
    int tid = threadIdx.x;
    int c2 = tid & 63;
    int grp = tid >> 6;
    const __half2* xb = (const __half2*)(g_xh + (size_t)b*ND);
    float ax = 0.f, ay = 0.f;
    for (int r = r0 + grp; r < r1; r += 4) {
        float2 f = __half22float2(xb[(size_t)r*64 + c2]);
        ax += f.x; ay += f.y;
    }
    __shared__ float sx[256], sy[256];
    sx[tid] = ax; sy[tid] = ay; __syncthreads();
    if (grp == 0) {
        float fx = sx[c2] + sx[c2+64] + sx[c2+128] + sx[c2+192];
        float fy = sy[c2] + sy[c2+64] + sy[c2+128] + sy[c2+192];
        float* dst = g_sembp + ((size_t)blockIdx.x*BNUM + b)*DDIM;
        dst[c2*2]   = fx;
        dst[c2*2+1] = fy;
    }
}

__global__ void k_beta(const float* __restrict__ W1, const float* __restrict__ b1,
                       const float* __restrict__ W3, const float* __restrict__ b3) {
    int b = blockIdx.x, d = threadIdx.x;
    __shared__ float semb[DDIM];
    float a = 0.f;
    for (int p = 0; p < RPARTS; p++) a += g_sembp[((size_t)p*BNUM + b)*DDIM + d];
    semb[d] = a; __syncthreads();
    float acc = b1[d];
    for (int k = 0; k < DDIM; k++) acc += semb[k] * W1[k*DDIM + d];
    float v = fmaxf(acc, 0.f) * W3[d];
    __shared__ float sh[DDIM];
    sh[d] = v; __syncthreads();
    for (int off = 64; off > 0; off >>= 1) {
        if (d < off) sh[d] += sh[d+off];
        __syncthreads();
    }
    if (d == 0) g_rs[b] = sh[0] + b3[0];
}

// ---------------- launch ----------------
extern "C" void kernel_launch(void* const* d_in, const int* in_sizes, int n_in,
                              void* d_out, int out_size) {
    const float* state = (const float*)d_in[0];
    const float* struc = (const float*)d_in[1];
    const int*   ei    = (const int*)d_in[2];
    const float* gatW  = (const float*)d_in[3];
    const float* attS  = (const float*)d_in[4];
    const float* attD  = (const float*)d_in[5];
    const float* Wns   = (const float*)d_in[6];
    const float* bns   = (const float*)d_in[7];
    const float* bias  = (const float*)d_in[8];
    const float* W1    = (const float*)d_in[9];
    const float* b1    = (const float*)d_in[10];
    const float* W2    = (const float*)d_in[11];
    const float* b2    = (const float*)d_in[12];
    const float* W3    = (const float*)d_in[13];
    const float* b3    = (const float*)d_in[14];
    float* out = (float*)d_out;
    int Etot = in_sizes[2] / 2;

    k_init<<<107, 256>>>(gatW, W2, Wns, bns);
    k_hist<<<(Etot+255)/256, 256>>>(ei, Etot);
    k_scan<<<1, 1024>>>(Etot);
    k_scatter<<<(Etot+255)/256, 256>>>(ei, Etot);

    dim3 ggrid((NNODE + 63)/64, BNUM);
    for (int l = 0; l < 3; l++) {
        k_gemm<0><<<ggrid, 256>>>(l, struc, state, attS + l*DDIM, attD + l*DDIM,
                                  nullptr, nullptr, nullptr);
        k_edge<<<(NNODE*32 + 255)/256, 256>>>(bias + l*DDIM);
    }

    k_reduce<<<dim3(RPARTS, BNUM), 256>>>();
    k_beta<<<BNUM, 128>>>(W1, b1, W3, b3);
    k_gemm<1><<<ggrid, 256>>>(3, nullptr, state, nullptr, nullptr, b2, W3, out);
}

// round 8
// speedup vs baseline: 1.0094x; 1.0094x over previous
#include <cuda_runtime.h>
#include <cuda_fp16.h>
#include <cstdint>

#define NNODE 10000
#define BNUM  4
#define DDIM  128
#define ECAP  262144
#define ND    (NNODE*DDIM)
#define SLOPE 0.01f
#define RPARTS 40

// ---------------- scratch (device globals; no allocation) ----------------
__device__ __align__(16) __half g_xh[BNUM*ND];   // layer activations (fp16, per-batch)
__device__ __align__(16) __half g_Wh[4*DDIM*DDIM]; // gatW[0..2], W2 as fp16
__device__ __align__(16) __half g_h[BNUM*ND];    // per-layer hidden h (fp16, per-batch)
__device__ __align__(16) float g_asrcT[NNODE*4]; // [n][b] transposed logits
__device__ __align__(16) float g_adstT[NNODE*4];
__device__ int   g_offs[NNODE+1];
__device__ int   g_cur[NNODE];
__device__ int   g_srcs[ECAP];
__device__ float g_wnsW[3*DDIM];
__device__ float g_bnsW[3*DDIM];
__device__ float g_sembp[RPARTS*BNUM*DDIM];
__device__ float g_rs[BNUM];

// ---------------- mma helpers ----------------
__device__ __forceinline__ uint32_t su(const void* p) {
    return (uint32_t)__cvta_generic_to_shared(p);
}
__device__ __forceinline__ void ldsm4(uint32_t& r0, uint32_t& r1, uint32_t& r2,
                                      uint32_t& r3, uint32_t addr) {
    asm volatile("ldmatrix.sync.aligned.m8n8.x4.shared.b16 {%0,%1,%2,%3}, [%4];"
                 : "=r"(r0), "=r"(r1), "=r"(r2), "=r"(r3) : "r"(addr));
}
__device__ __forceinline__ void ldsm4t(uint32_t& r0, uint32_t& r1, uint32_t& r2,
                                       uint32_t& r3, uint32_t addr) {
    asm volatile("ldmatrix.sync.aligned.m8n8.x4.trans.shared.b16 {%0,%1,%2,%3}, [%4];"
                 : "=r"(r0), "=r"(r1), "=r"(r2), "=r"(r3) : "r"(addr));
}
__device__ __forceinline__ void mma16816(float* c, uint32_t a0, uint32_t a1,
                                         uint32_t a2, uint32_t a3,
                                         uint32_t b0, uint32_t b1) {
    asm volatile(
        "mma.sync.aligned.m16n8k16.row.col.f32.f16.f16.f32 "
        "{%0,%1,%2,%3}, {%4,%5,%6,%7}, {%8,%9}, {%0,%1,%2,%3};"
        : "+f"(c[0]), "+f"(c[1]), "+f"(c[2]), "+f"(c[3])
        : "r"(a0), "r"(a1), "r"(a2), "r"(a3), "r"(b0), "r"(b1));
}

// ---------------- init: prep + zero + weight fp16 conversion ----------------
__global__ void k_init(const float* __restrict__ W, const float* __restrict__ W2,
                       const float* __restrict__ Wns, const float* __restrict__ bns) {
    int bb = blockIdx.x;
    if (bb < 3) {
        int l = bb, c = threadIdx.x;
        if (c < DDIM) {
            const float* Wl = W + l*DDIM*DDIM;
            float aw = 0.f, ab = 0.f;
            for (int k = 0; k < DDIM; k++) {
                float w = Wl[k*DDIM + c];
                aw += Wns[l*DDIM + k]*w;
                ab += bns[l*DDIM + k]*w;
            }
            g_wnsW[l*DDIM + c] = aw;
            g_bnsW[l*DDIM + c] = ab;
        }
    } else if (bb < 43) {
        int i = (bb - 3)*256 + threadIdx.x;
        if (i < NNODE) g_cur[i] = 0;
    } else {
        int i0 = (bb - 43)*1024 + threadIdx.x*4;
        int m = i0 >> 14, off = i0 & 16383;
        const float* src = (m < 3) ? (W + m*16384 + off) : (W2 + off);
        float4 v = *(const float4*)src;
        union { __half2 h[2]; uint2 u; } cv;
        cv.h[0] = __floats2half2_rn(v.x, v.y);
        cv.h[1] = __floats2half2_rn(v.z, v.w);
        *(uint2*)&g_Wh[i0] = cv.u;
    }
}

// ---------------- CSR build ----------------
__global__ void k_hist(const int* __restrict__ ei, int Etot) {
    int e = blockIdx.x*blockDim.x + threadIdx.x;
    if (e < Etot) atomicAdd(&g_cur[ei[Etot + e]], 1);
}
__global__ void k_scan(int Etot) {
    __shared__ int sh[1024];
    const int ITEMS = 10;
    int t = threadIdx.x;
    int base = t*ITEMS;
    int loc[ITEMS]; int sum = 0;
#pragma unroll
    for (int i = 0; i < ITEMS; i++) {
        int idx = base + i;
        int v = (idx < NNODE) ? g_cur[idx] : 0;
        loc[i] = sum; sum += v;
    }
    sh[t] = sum; __syncthreads();
    for (int off = 1; off < 1024; off <<= 1) {
        int v = (t >= off) ? sh[t-off] : 0;
        __syncthreads();
        sh[t] += v;
        __syncthreads();
    }
    int pre = t ? sh[t-1] : 0;
#pragma unroll
    for (int i = 0; i < ITEMS; i++) {
        int idx = base + i;
        if (idx < NNODE) { int o = pre + loc[i]; g_offs[idx] = o; g_cur[idx] = o; }
    }
    if (t == 1023) g_offs[NNODE] = sh[1023];
}
__global__ void k_scatter(const int* __restrict__ ei, int Etot) {
    int e = blockIdx.x*blockDim.x + threadIdx.x;
    if (e < Etot) {
        int d = ei[Etot + e];
        int pos = atomicAdd(&g_cur[d], 1);
        g_srcs[pos] = ei[e];
    }
}

// ---------------- HMMA GEMM (64x128 tile, fp16 in / fp32 acc) ----------------
#define AS_STR 72
#define BS_STR 136
template<int MODE>
__global__ void __launch_bounds__(256)
k_gemm(int widx, const float* __restrict__ strucf,
       const float* __restrict__ state,
       const float* __restrict__ attS, const float* __restrict__ attD,
       const float* __restrict__ b2, const float* __restrict__ W3,
       float* __restrict__ out) {
    __shared__ __align__(16) unsigned char smraw[35840];
    __half* As = (__half*)smraw;                    // [64][72]
    __half* Bs = (__half*)(smraw + 9216);           // [64][136]
    float*  acc_s = (float*)smraw;                  // [64][132] (reused)
    float*  pb = (float*)(smraw + 33792);           // 512 floats of params

    const int tid = threadIdx.x;
    const int lane = tid & 31, warp = tid >> 5;
    const int warpM = warp & 3, warpN = warp >> 2;
    const int b = blockIdx.y;
    const int rowbase = blockIdx.x * 64;

    const size_t xboff = (size_t)b * (size_t)ND;
    const __half* Wh = g_Wh + (size_t)widx * DDIM * DDIM;

    for (int i = tid; i < 512; i += 256) {
        int a = i >> 7, c = i & 127;
        float v;
        if (MODE == 0)
            v = (a == 0) ? g_wnsW[widx*DDIM + c] :
                (a == 1) ? g_bnsW[widx*DDIM + c] :
                (a == 2) ? attS[c] : attD[c];
        else
            v = (a == 0) ? b2[c] : (a == 1) ? W3[DDIM + c] : 0.f;
        pb[i] = v;
    }

    float acc[8][4];
#pragma unroll
    for (int i = 0; i < 8; i++)
#pragma unroll
        for (int j = 0; j < 4; j++) acc[i][j] = 0.f;

    const uint32_t asb = su(As), bsb = su(Bs);

#pragma unroll
    for (int kc = 0; kc < 2; ++kc) {
#pragma unroll
        for (int c = tid; c < 512; c += 256) {
            int r = c >> 3, q = c & 7;
            int rowg = rowbase + r; rowg = rowg < NNODE ? rowg : NNODE-1;
            if (MODE == 0 && widx == 0) {
                // layer 0: read strucEmb fp32 directly, convert on the fly
                const float* srow = strucf + (size_t)rowg*DDIM + kc*64 + q*8;
                float4 v0 = *(const float4*)srow;
                float4 v1 = *(const float4*)(srow + 4);
                union { __half2 h[4]; uint4 u; } cv;
                cv.h[0] = __floats2half2_rn(v0.x, v0.y);
                cv.h[1] = __floats2half2_rn(v0.z, v0.w);
                cv.h[2] = __floats2half2_rn(v1.x, v1.y);
                cv.h[3] = __floats2half2_rn(v1.z, v1.w);
                *(uint4*)&As[r*AS_STR + q*8] = cv.u;
            } else {
                uint4 v = *(const uint4*)(g_xh + xboff + (size_t)rowg*DDIM + kc*64 + q*8);
                *(uint4*)&As[r*AS_STR + q*8] = v;
            }
        }
#pragma unroll
        for (int c = tid; c < 1024; c += 256) {
            int r = c >> 4, q = c & 15;
            *(uint4*)&Bs[r*BS_STR + q*8] = *(const uint4*)(Wh + (size_t)(kc*64 + r)*DDIM + q*8);
        }
        __syncthreads();
#pragma unroll
        for (int ks = 0; ks < 4; ++ks) {
            uint32_t a0, a1, a2, a3;
            uint32_t aaddr = asb + ((warpM*16 + (lane & 15))*AS_STR
                                    + ks*16 + ((lane >> 4) << 3)) * 2;
            ldsm4(a0, a1, a2, a3, aaddr);
#pragma unroll
            for (int nt = 0; nt < 4; ++nt) {
                uint32_t b0, b1, b2r, b3;
                uint32_t baddr = bsb + ((ks*16 + (lane & 15))*BS_STR
                                        + warpN*64 + nt*16 + ((lane >> 4) << 3)) * 2;
                ldsm4t(b0, b1, b2r, b3, baddr);
                mma16816(acc[nt*2],   a0, a1, a2, a3, b0, b1);
                mma16816(acc[nt*2+1], a0, a1, a2, a3, b2r, b3);
            }
        }
        __syncthreads();
    }

    {
        int gr = warpM*16 + (lane >> 2);
        int cb0 = warpN*64 + (lane & 3)*2;
#pragma unroll
        for (int nt8 = 0; nt8 < 8; ++nt8) {
            int cb = cb0 + nt8*8;
            acc_s[gr*132 + cb]       = acc[nt8][0];
            acc_s[gr*132 + cb + 1]   = acc[nt8][1];
            acc_s[(gr+8)*132 + cb]   = acc[nt8][2];
            acc_s[(gr+8)*132 + cb+1] = acc[nt8][3];
        }
    }
    __syncthreads();

    const int r = tid >> 2, seg = tid & 3;
    const int row_g = rowbase + r;
    const int rc = row_g < NNODE ? row_g : NNODE-1;

    if (MODE == 0) {
        float st = state[(size_t)b*NNODE + rc];
        float asr = 0.f, ads = 0.f;
        uint32_t hw[16];
#pragma unroll
        for (int i2 = 0; i2 < 16; i2++) {
            int c = seg*32 + i2*2;
            float v0 = acc_s[r*132 + c]     + st*pb[c]     + pb[128 + c];
            float v1 = acc_s[r*132 + c + 1] + st*pb[c + 1] + pb[129 + c];
            asr += v0*pb[256 + c] + v1*pb[257 + c];
            ads += v0*pb[384 + c] + v1*pb[385 + c];
            __half2 h = __floats2half2_rn(v0, v1);
            hw[i2] = *(uint32_t*)&h;
        }
        asr += __shfl_xor_sync(0xffffffffu, asr, 1);
        asr += __shfl_xor_sync(0xffffffffu, asr, 2);
        ads += __shfl_xor_sync(0xffffffffu, ads, 1);
        ads += __shfl_xor_sync(0xffffffffu, ads, 2);
        if (row_g < NNODE) {
            if (seg == 0) {
                g_asrcT[row_g*4 + b] = asr;
                g_adstT[row_g*4 + b] = ads;
            }
            uint4* dst = (uint4*)(g_h + (size_t)b*ND + (size_t)row_g*DDIM + seg*32);
            const uint4* s4 = (const uint4*)hw;
            dst[0] = s4[0]; dst[1] = s4[1]; dst[2] = s4[2]; dst[3] = s4[3];
        }
    } else {
        float ra = 0.f;
#pragma unroll
        for (int i = 0; i < 32; i++) {
            int c = seg*32 + i;
            float v = fmaxf(acc_s[r*132 + c] + pb[c], 0.f);
            ra += v * pb[128 + c];
        }
        ra += __shfl_xor_sync(0xffffffffu, ra, 1);
        ra += __shfl_xor_sync(0xffffffffu, ra, 2);
        if (seg == 0 && row_g < NNODE)
            out[(size_t)b*NNODE + row_g] = g_rs[b] + ra;
    }
}

// ---------------- edge softmax + aggregate ----------------
// One warp per dst node, 4 batches fused, per-batch h layout (R5 proven),
// unroll-by-2 with pipelined pair prefetch (deeper MLP).
struct EdgeD { float4 as; uint2 h0, h1, h2, h3; };

__device__ __forceinline__ void load_edge(int e, int lane, EdgeD& d) {
    int sv = __ldg(&g_srcs[e]);
    d.as = *(const float4*)&g_asrcT[sv*4];
    const __half* hr = g_h + (size_t)sv*DDIM + lane*4;
    d.h0 = *(const uint2*)(hr);
    d.h1 = *(const uint2*)(hr + ND);
    d.h2 = *(const uint2*)(hr + 2*(size_t)ND);
    d.h3 = *(const uint2*)(hr + 3*(size_t)ND);
}

__device__ __forceinline__ void edge_acc(float a, float ad, uint2 hv,
                                         float4& acc, float& s) {
    float ae = a + ad;
    ae = ae > 0.f ? ae : SLOPE*ae;
    float p = __expf(ae);
    s += p;
    union { uint2 u; __half2 h[2]; } c; c.u = hv;
    float2 f0 = __half22float2(c.h[0]);
    float2 f1 = __half22float2(c.h[1]);
    acc.x += p*f0.x; acc.y += p*f0.y;
    acc.z += p*f1.x; acc.w += p*f1.y;
}

__device__ __forceinline__ void consume(const EdgeD& d, const float4& ad,
                                        float4& a0, float4& a1, float4& a2, float4& a3,
                                        float& s0, float& s1, float& s2, float& s3) {
    edge_acc(d.as.x, ad.x, d.h0, a0, s0);
    edge_acc(d.as.y, ad.y, d.h1, a1, s1);
    edge_acc(d.as.z, ad.z, d.h2, a2, s2);
    edge_acc(d.as.w, ad.w, d.h3, a3, s3);
}

__global__ void __launch_bounds__(256) k_edge(const float* __restrict__ bias) {
    int n = (blockIdx.x*blockDim.x + threadIdx.x) >> 5;
    int lane = threadIdx.x & 31;
    if (n >= NNODE) return;
    int e0 = g_offs[n], e1 = g_offs[n+1];
    const float4 ad = *(const float4*)&g_adstT[n*4];
    const float4 bi = ((const float4*)bias)[lane];

    float4 acc0 = {0,0,0,0}, acc1 = {0,0,0,0}, acc2 = {0,0,0,0}, acc3 = {0,0,0,0};
    float s0 = 0.f, s1 = 0.f, s2 = 0.f, s3 = 0.f;

    EdgeD c0, c1;
    load_edge(e0, lane, c0);
    bool has1 = (e0 + 1 < e1);
    if (has1) load_edge(e0 + 1, lane, c1);

    for (int e = e0;;) {
        int en = e + 2;
        EdgeD n0, n1;
        bool v0 = en < e1, v1 = en + 1 < e1;
        if (v0) load_edge(en, lane, n0);
        if (v1) load_edge(en + 1, lane, n1);
        consume(c0, ad, acc0, acc1, acc2, acc3, s0, s1, s2, s3);
        if (has1) consume(c1, ad, acc0, acc1, acc2, acc3, s0, s1, s2, s3);
        if (!v0) break;
        c0 = n0; c1 = n1; has1 = v1;
        e = en;
    }

    float4* accs[4] = {&acc0, &acc1, &acc2, &acc3};
    float ss[4] = {s0, s1, s2, s3};
#pragma unroll
    for (int b = 0; b < 4; b++) {
        float inv = 1.f / ss[b];
        float4 a = *accs[b];
        union { uint2 u; __half2 h[2]; } ov;
        ov.h[0] = __floats2half2_rn(fmaxf(a.x*inv + bi.x, 0.f),
                                    fmaxf(a.y*inv + bi.y, 0.f));
        ov.h[1] = __floats2half2_rn(fmaxf(a.z*inv + bi.z, 0.f),
                                    fmaxf(a.w*inv + bi.w, 0.f));
        *(uint2*)(g_xh + (size_t)b*ND + (size_t)n*DDIM + lane*4) = ov.u;
    }
}

// ---------------- final head ----------------
__global__ void k_reduce() {
    int b = blockIdx.y;
    int r0 = blockIdx.x * 250;
    int r1 = r0 + 250; if (r1 > NNODE) r1 = NNODE;
    int tid = threadIdx.x;
    int c2 = tid & 63;
    int grp = tid >> 6;
    const __half2* xb = (const __half2*)(g_xh + (size_t)b*ND);
    float ax = 0.f, ay = 0.f;
    for (int r = r0 + grp; r < r1; r += 4) {
        float2 f = __half22float2(xb[(size_t)r*64 + c2]);
        ax += f.x; ay += f.y;
    }
    __shared__ float sx[256], sy[256];
    sx[tid] = ax; sy[tid] = ay; __syncthreads();
    if (grp == 0) {
        float fx = sx[c2] + sx[c2+64] + sx[c2+128] + sx[c2+192];
        float fy = sy[c2] + sy[c2+64] + sy[c2+128] + sy[c2+192];
        float* dst = g_sembp + ((size_t)blockIdx.x*BNUM + b)*DDIM;
        dst[c2*2]   = fx;
        dst[c2*2+1] = fy;
    }
}

__global__ void k_beta(const float* __restrict__ W1, const float* __restrict__ b1,
                       const float* __restrict__ W3, const float* __restrict__ b3) {
    int b = blockIdx.x, d = threadIdx.x;
    __shared__ float semb[DDIM];
    float a = 0.f;
    for (int p = 0; p < RPARTS; p++) a += g_sembp[((size_t)p*BNUM + b)*DDIM + d];
    semb[d] = a; __syncthreads();
    float acc = b1[d];
    for (int k = 0; k < DDIM; k++) acc += semb[k] * W1[k*DDIM + d];
    float v = fmaxf(acc, 0.f) * W3[d];
    __shared__ float sh[DDIM];
    sh[d] = v; __syncthreads();
    for (int off = 64; off > 0; off >>= 1) {
        if (d < off) sh[d] += sh[d+off];
        __syncthreads();
    }
    if (d == 0) g_rs[b] = sh[0] + b3[0];
}

// ---------------- launch ----------------
extern "C" void kernel_launch(void* const* d_in, const int* in_sizes, int n_in,
                              void* d_out, int out_size) {
    const float* state = (const float*)d_in[0];
    const float* struc = (const float*)d_in[1];
    const int*   ei    = (const int*)d_in[2];
    const float* gatW  = (const float*)d_in[3];
    const float* attS  = (const float*)d_in[4];
    const float* attD  = (const float*)d_in[5];
    const float* Wns   = (const float*)d_in[6];
    const float* bns   = (const float*)d_in[7];
    const float* bias  = (const float*)d_in[8];
    const float* W1    = (const float*)d_in[9];
    const float* b1    = (const float*)d_in[10];
    const float* W2    = (const float*)d_in[11];
    const float* b2    = (const float*)d_in[12];
    const float* W3    = (const float*)d_in[13];
    const float* b3    = (const float*)d_in[14];
    float* out = (float*)d_out;
    int Etot = in_sizes[2] / 2;

    k_init<<<107, 256>>>(gatW, W2, Wns, bns);
    k_hist<<<(Etot+255)/256, 256>>>(ei, Etot);
    k_scan<<<1, 1024>>>(Etot);
    k_scatter<<<(Etot+255)/256, 256>>>(ei, Etot);

    dim3 ggrid((NNODE + 63)/64, BNUM);
    for (int l = 0; l < 3; l++) {
        k_gemm<0><<<ggrid, 256>>>(l, struc, state, attS + l*DDIM, attD + l*DDIM,
                                  nullptr, nullptr, nullptr);
        k_edge<<<(NNODE*32 + 255)/256, 256>>>(bias + l*DDIM);
    }

    k_reduce<<<dim3(RPARTS, BNUM), 256>>>();
    k_beta<<<BNUM, 128>>>(W1, b1, W3, b3);
    k_gemm<1><<<ggrid, 256>>>(3, nullptr, state, nullptr, nullptr, b2, W3, out);
}

// round 9
// speedup vs baseline: 1.1157x; 1.1053x over previous
#include <cuda_runtime.h>
#include <cuda_fp16.h>
#include <cstdint>

#define NNODE 10000
#define BNUM  4
#define DDIM  128
#define ECAP  262144
#define ND    (NNODE*DDIM)
#define SLOPE 0.01f

// ---------------- scratch (device globals; no allocation) ----------------
__device__ __align__(16) __half g_xh[BNUM*ND];   // layer activations (fp16, per-batch)
__device__ __align__(16) __half g_strh[ND];      // strucEmb fp16
__device__ __align__(16) __half g_Wh[4*DDIM*DDIM]; // gatW[0..2], W2 as fp16
__device__ __align__(16) __half g_h[BNUM*ND];    // per-layer hidden h (fp16, per-batch)
__device__ __align__(16) float g_asrcT[NNODE*4]; // [n][b] transposed logits
__device__ __align__(16) float g_adstT[NNODE*4];
__device__ int   g_offs[NNODE+1];
__device__ int   g_cur[NNODE];
__device__ int   g_srcs[ECAP];
__device__ float g_wnsW[3*DDIM];
__device__ float g_bnsW[3*DDIM];
__device__ float g_semb[BNUM*DDIM];
__device__ float g_rs[BNUM];

// ---------------- mma helpers ----------------
__device__ __forceinline__ uint32_t su(const void* p) {
    return (uint32_t)__cvta_generic_to_shared(p);
}
__device__ __forceinline__ void ldsm4(uint32_t& r0, uint32_t& r1, uint32_t& r2,
                                      uint32_t& r3, uint32_t addr) {
    asm volatile("ldmatrix.sync.aligned.m8n8.x4.shared.b16 {%0,%1,%2,%3}, [%4];"
                 : "=r"(r0), "=r"(r1), "=r"(r2), "=r"(r3) : "r"(addr));
}
__device__ __forceinline__ void ldsm4t(uint32_t& r0, uint32_t& r1, uint32_t& r2,
                                       uint32_t& r3, uint32_t addr) {
    asm volatile("ldmatrix.sync.aligned.m8n8.x4.trans.shared.b16 {%0,%1,%2,%3}, [%4];"
                 : "=r"(r0), "=r"(r1), "=r"(r2), "=r"(r3) : "r"(addr));
}
__device__ __forceinline__ void mma16816(float* c, uint32_t a0, uint32_t a1,
                                         uint32_t a2, uint32_t a3,
                                         uint32_t b0, uint32_t b1) {
    asm volatile(
        "mma.sync.aligned.m16n8k16.row.col.f32.f16.f16.f32 "
        "{%0,%1,%2,%3}, {%4,%5,%6,%7}, {%8,%9}, {%0,%1,%2,%3};"
        : "+f"(c[0]), "+f"(c[1]), "+f"(c[2]), "+f"(c[3])
        : "r"(a0), "r"(a1), "r"(a2), "r"(a3), "r"(b0), "r"(b1));
}

// ---------------- init: prep + zero + fp16 conversions ----------------
__global__ void k_init(const float* __restrict__ W, const float* __restrict__ W2,
                       const float* __restrict__ Wns, const float* __restrict__ bns,
                       const float* __restrict__ struc) {
    int bb = blockIdx.x;
    if (bb < 3) {
        int l = bb, c = threadIdx.x;
        if (c < DDIM) {
            const float* Wl = W + l*DDIM*DDIM;
            float aw = 0.f, ab = 0.f;
            for (int k = 0; k < DDIM; k++) {
                float w = Wl[k*DDIM + c];
                aw += Wns[l*DDIM + k]*w;
                ab += bns[l*DDIM + k]*w;
            }
            g_wnsW[l*DDIM + c] = aw;
            g_bnsW[l*DDIM + c] = ab;
        }
    } else if (bb < 43) {
        int i = (bb - 3)*256 + threadIdx.x;
        if (i < NNODE) g_cur[i] = 0;
        if (i < BNUM*DDIM) g_semb[i] = 0.f;
    } else if (bb < 107) {
        int i0 = (bb - 43)*1024 + threadIdx.x*4;
        int m = i0 >> 14, off = i0 & 16383;
        const float* src = (m < 3) ? (W + m*16384 + off) : (W2 + off);
        float4 v = *(const float4*)src;
        union { __half2 h[2]; uint2 u; } cv;
        cv.h[0] = __floats2half2_rn(v.x, v.y);
        cv.h[1] = __floats2half2_rn(v.z, v.w);
        *(uint2*)&g_Wh[i0] = cv.u;
    } else {
        int i0 = (bb - 107)*1024 + threadIdx.x*4;
        if (i0 < ND) {
            float4 v = *(const float4*)(struc + i0);
            union { __half2 h[2]; uint2 u; } cv;
            cv.h[0] = __floats2half2_rn(v.x, v.y);
            cv.h[1] = __floats2half2_rn(v.z, v.w);
            *(uint2*)&g_strh[i0] = cv.u;
        }
    }
}

// ---------------- CSR build ----------------
__global__ void k_hist(const int* __restrict__ ei, int Etot) {
    int e = blockIdx.x*blockDim.x + threadIdx.x;
    if (e < Etot) atomicAdd(&g_cur[ei[Etot + e]], 1);
}
__global__ void k_scan(int Etot) {
    __shared__ int sh[1024];
    const int ITEMS = 10;
    int t = threadIdx.x;
    int base = t*ITEMS;
    int loc[ITEMS]; int sum = 0;
#pragma unroll
    for (int i = 0; i < ITEMS; i++) {
        int idx = base + i;
        int v = (idx < NNODE) ? g_cur[idx] : 0;
        loc[i] = sum; sum += v;
    }
    sh[t] = sum; __syncthreads();
    for (int off = 1; off < 1024; off <<= 1) {
        int v = (t >= off) ? sh[t-off] : 0;
        __syncthreads();
        sh[t] += v;
        __syncthreads();
    }
    int pre = t ? sh[t-1] : 0;
#pragma unroll
    for (int i = 0; i < ITEMS; i++) {
        int idx = base + i;
        if (idx < NNODE) { int o = pre + loc[i]; g_offs[idx] = o; g_cur[idx] = o; }
    }
    if (t == 1023) g_offs[NNODE] = sh[1023];
}
__global__ void k_scatter(const int* __restrict__ ei, int Etot) {
    int e = blockIdx.x*blockDim.x + threadIdx.x;
    if (e < Etot) {
        int d = ei[Etot + e];
        int pos = atomicAdd(&g_cur[d], 1);
        g_srcs[pos] = ei[e];
    }
}

// ---------------- HMMA GEMM (64x128 tile, fp16 in / fp32 acc) ----------------
#define AS_STR 72
#define BS_STR 136
template<int MODE>
__global__ void __launch_bounds__(256)
k_gemm(int widx, const float* __restrict__ state,
       const float* __restrict__ attS, const float* __restrict__ attD,
       const float* __restrict__ b2, const float* __restrict__ W3,
       float* __restrict__ out) {
    __shared__ __align__(16) unsigned char smraw[35840];
    __half* As = (__half*)smraw;                    // [64][72]
    __half* Bs = (__half*)(smraw + 9216);           // [64][136]
    float*  acc_s = (float*)smraw;                  // [64][132] (reused)
    float*  pb = (float*)(smraw + 33792);           // 512 floats of params

    const int tid = threadIdx.x;
    const int lane = tid & 31, warp = tid >> 5;
    const int warpM = warp & 3, warpN = warp >> 2;
    const int b = blockIdx.y;
    const int rowbase = blockIdx.x * 64;

    const __half* xa = (widx == 0) ? g_strh : g_xh;
    const size_t xboff = (widx == 0) ? 0 : (size_t)b * (size_t)ND;
    const __half* Wh = g_Wh + (size_t)widx * DDIM * DDIM;

    for (int i = tid; i < 512; i += 256) {
        int a = i >> 7, c = i & 127;
        float v;
        if (MODE == 0)
            v = (a == 0) ? g_wnsW[widx*DDIM + c] :
                (a == 1) ? g_bnsW[widx*DDIM + c] :
                (a == 2) ? attS[c] : attD[c];
        else
            v = (a == 0) ? b2[c] : (a == 1) ? W3[DDIM + c] : 0.f;
        pb[i] = v;
    }

    float acc[8][4];
#pragma unroll
    for (int i = 0; i < 8; i++)
#pragma unroll
        for (int j = 0; j < 4; j++) acc[i][j] = 0.f;

    const uint32_t asb = su(As), bsb = su(Bs);

#pragma unroll
    for (int kc = 0; kc < 2; ++kc) {
#pragma unroll
        for (int c = tid; c < 512; c += 256) {
            int r = c >> 3, q = c & 7;
            int rowg = rowbase + r; rowg = rowg < NNODE ? rowg : NNODE-1;
            uint4 v = *(const uint4*)(xa + xboff + (size_t)rowg*DDIM + kc*64 + q*8);
            *(uint4*)&As[r*AS_STR + q*8] = v;
        }
#pragma unroll
        for (int c = tid; c < 1024; c += 256) {
            int r = c >> 4, q = c & 15;
            *(uint4*)&Bs[r*BS_STR + q*8] = *(const uint4*)(Wh + (size_t)(kc*64 + r)*DDIM + q*8);
        }
        __syncthreads();
#pragma unroll
        for (int ks = 0; ks < 4; ++ks) {
            uint32_t a0, a1, a2, a3;
            uint32_t aaddr = asb + ((warpM*16 + (lane & 15))*AS_STR
                                    + ks*16 + ((lane >> 4) << 3)) * 2;
            ldsm4(a0, a1, a2, a3, aaddr);
#pragma unroll
            for (int nt = 0; nt < 4; ++nt) {
                uint32_t b0, b1, b2r, b3;
                uint32_t baddr = bsb + ((ks*16 + (lane & 15))*BS_STR
                                        + warpN*64 + nt*16 + ((lane >> 4) << 3)) * 2;
                ldsm4t(b0, b1, b2r, b3, baddr);
                mma16816(acc[nt*2],   a0, a1, a2, a3, b0, b1);
                mma16816(acc[nt*2+1], a0, a1, a2, a3, b2r, b3);
            }
        }
        __syncthreads();
    }

    {
        int gr = warpM*16 + (lane >> 2);
        int cb0 = warpN*64 + (lane & 3)*2;
#pragma unroll
        for (int nt8 = 0; nt8 < 8; ++nt8) {
            int cb = cb0 + nt8*8;
            acc_s[gr*132 + cb]       = acc[nt8][0];
            acc_s[gr*132 + cb + 1]   = acc[nt8][1];
            acc_s[(gr+8)*132 + cb]   = acc[nt8][2];
            acc_s[(gr+8)*132 + cb+1] = acc[nt8][3];
        }
    }
    __syncthreads();

    const int r = tid >> 2, seg = tid & 3;
    const int row_g = rowbase + r;
    const int rc = row_g < NNODE ? row_g : NNODE-1;

    if (MODE == 0) {
        float st = state[(size_t)b*NNODE + rc];
        float asr = 0.f, ads = 0.f;
        uint32_t hw[16];
#pragma unroll
        for (int i2 = 0; i2 < 16; i2++) {
            int c = seg*32 + i2*2;
            float v0 = acc_s[r*132 + c]     + st*pb[c]     + pb[128 + c];
            float v1 = acc_s[r*132 + c + 1] + st*pb[c + 1] + pb[129 + c];
            asr += v0*pb[256 + c] + v1*pb[257 + c];
            ads += v0*pb[384 + c] + v1*pb[385 + c];
            __half2 h = __floats2half2_rn(v0, v1);
            hw[i2] = *(uint32_t*)&h;
        }
        asr += __shfl_xor_sync(0xffffffffu, asr, 1);
        asr += __shfl_xor_sync(0xffffffffu, asr, 2);
        ads += __shfl_xor_sync(0xffffffffu, ads, 1);
        ads += __shfl_xor_sync(0xffffffffu, ads, 2);
        if (row_g < NNODE) {
            if (seg == 0) {
                g_asrcT[row_g*4 + b] = asr;
                g_adstT[row_g*4 + b] = ads;
            }
            uint4* dst = (uint4*)(g_h + (size_t)b*ND + (size_t)row_g*DDIM + seg*32);
            const uint4* s4 = (const uint4*)hw;
            dst[0] = s4[0]; dst[1] = s4[1]; dst[2] = s4[2]; dst[3] = s4[3];
        }
    } else {
        float ra = 0.f;
#pragma unroll
        for (int i = 0; i < 32; i++) {
            int c = seg*32 + i;
            float v = fmaxf(acc_s[r*132 + c] + pb[c], 0.f);
            ra += v * pb[128 + c];
        }
        ra += __shfl_xor_sync(0xffffffffu, ra, 1);
        ra += __shfl_xor_sync(0xffffffffu, ra, 2);
        if (seg == 0 && row_g < NNODE)
            out[(size_t)b*NNODE + row_g] = g_rs[b] + ra;
    }
}

// ---------------- edge softmax + aggregate ----------------
// One warp per dst node, ALL 4 batches fused. Single pass, no max
// (logits are O(1): exp(ae)/sum(exp(ae)) is exact-ratio and overflow-safe).
// LAST=1: additionally accumulate node-sum of outputs into g_semb.
__device__ __forceinline__ void edge_acc(float a, float ad, uint2 hv,
                                         float4& acc, float& s) {
    float ae = a + ad;
    ae = ae > 0.f ? ae : SLOPE*ae;
    float p = __expf(ae);
    s += p;
    union { uint2 u; __half2 h[2]; } c; c.u = hv;
    float2 f0 = __half22float2(c.h[0]);
    float2 f1 = __half22float2(c.h[1]);
    acc.x += p*f0.x; acc.y += p*f0.y;
    acc.z += p*f1.x; acc.w += p*f1.y;
}

template<int LAST>
__global__ void __launch_bounds__(256) k_edge(const float* __restrict__ bias) {
    __shared__ float sacc[BNUM*DDIM];
    if (LAST) {
        sacc[threadIdx.x] = 0.f;
        sacc[threadIdx.x + 256] = 0.f;
        __syncthreads();
    }
    int n = (blockIdx.x*blockDim.x + threadIdx.x) >> 5;
    int lane = threadIdx.x & 31;
    if (n < NNODE) {
        int e0 = g_offs[n], e1 = g_offs[n+1];
        const float4 ad = *(const float4*)&g_adstT[n*4];

        float4 acc0 = {0,0,0,0}, acc1 = {0,0,0,0}, acc2 = {0,0,0,0}, acc3 = {0,0,0,0};
        float s0 = 0.f, s1 = 0.f, s2 = 0.f, s3 = 0.f;

        // depth-2 pipeline
        int sv = __ldg(&g_srcs[e0]);
        float4 as = *(const float4*)&g_asrcT[sv*4];
        const __half* hr = g_h + (size_t)sv*DDIM + lane*4;
        uint2 h0 = *(const uint2*)(hr);
        uint2 h1 = *(const uint2*)(hr + ND);
        uint2 h2 = *(const uint2*)(hr + 2*(size_t)ND);
        uint2 h3 = *(const uint2*)(hr + 3*(size_t)ND);

        for (int e = e0; e < e1; ++e) {
            float4 asc = as;
            uint2 c0 = h0, c1 = h1, c2 = h2, c3 = h3;
            if (e + 1 < e1) {
                sv = __ldg(&g_srcs[e+1]);
                as = *(const float4*)&g_asrcT[sv*4];
                hr = g_h + (size_t)sv*DDIM + lane*4;
                h0 = *(const uint2*)(hr);
                h1 = *(const uint2*)(hr + ND);
                h2 = *(const uint2*)(hr + 2*(size_t)ND);
                h3 = *(const uint2*)(hr + 3*(size_t)ND);
            }
            edge_acc(asc.x, ad.x, c0, acc0, s0);
            edge_acc(asc.y, ad.y, c1, acc1, s1);
            edge_acc(asc.z, ad.z, c2, acc2, s2);
            edge_acc(asc.w, ad.w, c3, acc3, s3);
        }

        float4 bi = ((const float4*)bias)[lane];
        float4* accs[4] = {&acc0, &acc1, &acc2, &acc3};
        float ss[4] = {s0, s1, s2, s3};
#pragma unroll
        for (int b = 0; b < 4; b++) {
            float inv = 1.f / ss[b];
            float4 a = *accs[b];
            float o0 = fmaxf(a.x*inv + bi.x, 0.f);
            float o1 = fmaxf(a.y*inv + bi.y, 0.f);
            float o2 = fmaxf(a.z*inv + bi.z, 0.f);
            float o3 = fmaxf(a.w*inv + bi.w, 0.f);
            union { uint2 u; __half2 h[2]; } ov;
            ov.h[0] = __floats2half2_rn(o0, o1);
            ov.h[1] = __floats2half2_rn(o2, o3);
            *(uint2*)(g_xh + (size_t)b*ND + (size_t)n*DDIM + lane*4) = ov.u;
            if (LAST) {
                int cb = b*DDIM + lane*4;
                atomicAdd(&sacc[cb],     o0);
                atomicAdd(&sacc[cb + 1], o1);
                atomicAdd(&sacc[cb + 2], o2);
                atomicAdd(&sacc[cb + 3], o3);
            }
        }
    }
    if (LAST) {
        __syncthreads();
        atomicAdd(&g_semb[threadIdx.x],       sacc[threadIdx.x]);
        atomicAdd(&g_semb[threadIdx.x + 256], sacc[threadIdx.x + 256]);
    }
}

// ---------------- final head ----------------
__global__ void k_beta(const float* __restrict__ W1, const float* __restrict__ b1,
                       const float* __restrict__ W3, const float* __restrict__ b3) {
    int b = blockIdx.x, d = threadIdx.x;
    __shared__ float semb[DDIM];
    semb[d] = g_semb[b*DDIM + d];
    __syncthreads();
    float acc = b1[d];
    for (int k = 0; k < DDIM; k++) acc += semb[k] * W1[k*DDIM + d];
    float v = fmaxf(acc, 0.f) * W3[d];
    __shared__ float sh[DDIM];
    sh[d] = v; __syncthreads();
    for (int off = 64; off > 0; off >>= 1) {
        if (d < off) sh[d] += sh[d+off];
        __syncthreads();
    }
    if (d == 0) g_rs[b] = sh[0] + b3[0];
}

// ---------------- launch ----------------
extern "C" void kernel_launch(void* const* d_in, const int* in_sizes, int n_in,
                              void* d_out, int out_size) {
    const float* state = (const float*)d_in[0];
    const float* struc = (const float*)d_in[1];
    const int*   ei    = (const int*)d_in[2];
    const float* gatW  = (const float*)d_in[3];
    const float* attS  = (const float*)d_in[4];
    const float* attD  = (const float*)d_in[5];
    const float* Wns   = (const float*)d_in[6];
    const float* bns   = (const float*)d_in[7];
    const float* bias  = (const float*)d_in[8];
    const float* W1    = (const float*)d_in[9];
    const float* b1    = (const float*)d_in[10];
    const float* W2    = (const float*)d_in[11];
    const float* b2    = (const float*)d_in[12];
    const float* W3    = (const float*)d_in[13];
    const float* b3    = (const float*)d_in[14];
    float* out = (float*)d_out;
    int Etot = in_sizes[2] / 2;

    k_init<<<107 + ND/1024, 256>>>(gatW, W2, Wns, bns, struc);
    k_hist<<<(Etot+255)/256, 256>>>(ei, Etot);
    k_scan<<<1, 1024>>>(Etot);
    k_scatter<<<(Etot+255)/256, 256>>>(ei, Etot);

    dim3 ggrid((NNODE + 63)/64, BNUM);
    for (int l = 0; l < 3; l++) {
        k_gemm<0><<<ggrid, 256>>>(l, state, attS + l*DDIM, attD + l*DDIM,
                                  nullptr, nullptr, nullptr);
        if (l < 2) k_edge<0><<<(NNODE*32 + 255)/256, 256>>>(bias + l*DDIM);
        else       k_edge<1><<<(NNODE*32 + 255)/256, 256>>>(bias + l*DDIM);
    }

    k_beta<<<BNUM, 128>>>(W1, b1, W3, b3);
    k_gemm<1><<<ggrid, 256>>>(3, state, nullptr, nullptr, b2, W3, out);
}